// round 8
// baseline (speedup 1.0000x reference)
#include <cuda_runtime.h>
#include <cuda_bf16.h>
#include <cstdint>

// Real spherical harmonics up to L=20 -> 441 cols/point, N=500k, fp32 out.
// 882 MB of output => HBM-write-bound.
//
// Round-8 probe: MORE, SMALLER CTA store-slots per SM.
//  * TILE=16 points -> smem 28224 B -> 7 CTAs/SM (vs 4 at TILE=32).
//    Finer phase-staggering of store bursts across slots; DRAM gaps when
//    all slots sit in compute/drain shrink.
//  * 128 threads: point = t&15, m-residue w = t>>4 (mod 8 split). Each warp
//    serializes two residue chains (half-warp divergence) — acceptable,
//    r7 proved compute latency is slack.
//  - All recurrence coefficients + norms are compile-time immediates.
//  - Scatter STS stride 441 words (odd) => conflict-free within half-warp.
//  - One 28224 B cp.async.bulk store per tile; wait_group.read before exit.

#define SH_L 20
#define SH_K 441
#define TILE 16
#define THREADS 128
#define SMEM_BYTES (TILE * SH_K * 4)   // 28224

// ---------- compile-time math ----------
__host__ __device__ constexpr double kPI_c() { return 3.141592653589793238462643383279502884; }

__host__ __device__ constexpr double csqrt(double x) {
    double g = (x > 1.0) ? x : 1.0;
    for (int i = 0; i < 200; ++i) g = 0.5 * (g + x / g);
    return g;
}

__host__ __device__ constexpr double inv_ratio(int l, int m) {
    double p = 1.0;
    for (int k = l - m + 1; k <= l + m; ++k) p *= (double)k;
    return p;
}

template <int L_, int M>
__host__ __device__ constexpr float nf_val() {
    double norm = csqrt((2.0 * L_ + 1.0) / (4.0 * kPI_c()) / inv_ratio(L_, M));
    return (float)(M > 0 ? norm * csqrt(2.0) : norm);
}

// prod_{j=1..8} (2(M+j)-1): 8-step P_mm jump factor (even # of CS negations)
template <int M>
__host__ __device__ constexpr float f8_val() {
    double p = 1.0;
    for (int j = 1; j <= 8; ++j) p *= (double)(2 * (M + j) - 1);
    return (float)p;
}

// ---------- store helpers ----------
template <int M, int L_>
__device__ __forceinline__ void storepair(float* __restrict__ row, float b,
                                          float cm, float sm) {
    if constexpr (M == 0) {
        row[L_ * (L_ + 1)] = b;
    } else {
        row[L_ * (L_ + 1) + M] = b * cm;
        row[L_ * (L_ + 1) - M] = b * sm;
    }
}

// ---------- l recursion for fixed m ----------
template <int M, int L_>
__device__ __forceinline__ void lstep(float* __restrict__ row, float ct,
                                      float cm, float sm, float p1, float p2) {
    constexpr float A = (float)((double)(2 * L_ - 1) / (double)(L_ - M));
    constexpr float B = (float)(-(double)(L_ + M - 1) / (double)(L_ - M));
    const float pv = fmaf(A * ct, p1, B * p2);
    constexpr float NF = nf_val<L_, M>();
    storepair<M, L_>(row, NF * pv, cm, sm);
    if constexpr (L_ < SH_L) lstep<M, L_ + 1>(row, ct, cm, sm, pv, p1);
}

// ---------- m chain: one residue class mod 8 ----------
template <int M>
__device__ __forceinline__ void mchain(float* __restrict__ row, float ct,
                                       float st8, float c8, float s8,
                                       float pmm, float cm, float sm) {
    constexpr float NF0 = nf_val<M, M>();
    storepair<M, M>(row, NF0 * pmm, cm, sm);
    if constexpr (M < SH_L) {
        constexpr float C1 = (float)(2 * M + 1);
        const float p1 = (C1 * ct) * pmm;
        constexpr float NF1 = nf_val<M + 1, M>();
        storepair<M, M + 1>(row, NF1 * p1, cm, sm);
        if constexpr (M + 2 <= SH_L) lstep<M, M + 2>(row, ct, cm, sm, p1, pmm);
    }
    if constexpr (M + 8 <= SH_L) {
        constexpr float F = f8_val<M>();
        const float pmm2 = (pmm * F) * st8;
        const float cn = fmaf(cm, c8, -(sm * s8));
        const float sn = fmaf(sm, c8, cm * s8);
        mchain<M + 8>(row, ct, st8, c8, s8, pmm2, cn, sn);
    }
}

__device__ __forceinline__ uint32_t smem_u32(const void* p) {
    uint32_t a;
    asm("{ .reg .u64 t; cvta.to.shared.u64 t, %1; cvt.u32.u64 %0, t; }"
        : "=r"(a) : "l"(p));
    return a;
}

// ---------- kernel ----------
__global__ void __launch_bounds__(THREADS, 8)
sph_harm_kernel(const float* __restrict__ coords, float* __restrict__ out, int n)
{
    extern __shared__ float sh[];           // TILE * SH_K floats
    const int base = blockIdx.x * TILE;
    const int t = threadIdx.x;
    const int lane = t & 15;                // point within tile
    const int w = t >> 4;                   // m residue (0..7)
    const int p = base + lane;

    if (p < n) {
        const float x = coords[3 * p + 0];
        const float y = coords[3 * p + 1];
        const float z = coords[3 * p + 2];

        const float r = sqrtf(x * x + y * y + z * z);
        float ct = z / r;
        ct = fminf(1.0f, fmaxf(-1.0f, ct));
        const float st = sqrtf(fmaxf(1.0f - ct * ct, 0.0f));
        const float st2 = st * st;
        const float st4 = st2 * st2;
        const float st8 = st4 * st4;

        const float rho2 = x * x + y * y;
        float c1, s1;
        if (rho2 > 0.0f) {
            const float ir = rsqrtf(rho2);
            c1 = x * ir;
            s1 = y * ir;
        } else {
            c1 = 1.0f;
            s1 = 0.0f;
        }
        const float c2 = fmaf(c1, c1, -(s1 * s1));
        const float s2 = 2.0f * c1 * s1;
        const float c4 = fmaf(c2, c2, -(s2 * s2));
        const float s4 = 2.0f * c2 * s2;
        const float c8 = fmaf(c4, c4, -(s4 * s4));
        const float s8 = 2.0f * c4 * s4;

        float* row = sh + lane * SH_K;

        switch (w) {
        case 0:
            mchain<0>(row, ct, st8, c8, s8, 1.0f, 1.0f, 0.0f);
            break;
        case 1:
            mchain<1>(row, ct, st8, c8, s8, -st, c1, s1);
            break;
        case 2:
            mchain<2>(row, ct, st8, c8, s8, 3.0f * st2, c2, s2);
            break;
        case 3: {
            const float c3 = fmaf(c2, c1, -(s2 * s1));
            const float s3 = fmaf(s2, c1, c2 * s1);
            mchain<3>(row, ct, st8, c8, s8, -15.0f * st2 * st, c3, s3);
            break;
        }
        case 4:
            mchain<4>(row, ct, st8, c8, s8, 105.0f * st4, c4, s4);
            break;
        case 5: {
            const float c5 = fmaf(c4, c1, -(s4 * s1));
            const float s5 = fmaf(s4, c1, c4 * s1);
            mchain<5>(row, ct, st8, c8, s8, -945.0f * st4 * st, c5, s5);
            break;
        }
        case 6: {
            const float c6 = fmaf(c4, c2, -(s4 * s2));
            const float s6 = fmaf(s4, c2, c4 * s2);
            mchain<6>(row, ct, st8, c8, s8, 10395.0f * st4 * st2, c6, s6);
            break;
        }
        default: {
            const float c3 = fmaf(c2, c1, -(s2 * s1));
            const float s3 = fmaf(s2, c1, c2 * s1);
            const float c7 = fmaf(c4, c3, -(s4 * s3));
            const float s7 = fmaf(s4, c3, c4 * s3);
            mchain<7>(row, ct, st8, c8, s8, -135135.0f * st4 * st2 * st, c7, s7);
            break;
        }
        }
    }

    // make STS visible to the async proxy, then sync the tile
    asm volatile("fence.proxy.async.shared::cta;" ::: "memory");
    __syncthreads();

    const int npts = min(TILE, n - base);
    if (npts <= 0) return;
    float* gbase = out + (size_t)base * SH_K;

    if (npts == TILE) {
        // full tile: single bulk TMA store (28224 B, 16B-aligned both sides)
        if (t == 0) {
            const uint32_t saddr = smem_u32(sh);
            asm volatile(
                "cp.async.bulk.global.shared::cta.bulk_group [%0], [%1], %2;"
                :: "l"(gbase), "r"(saddr), "r"((uint32_t)SMEM_BYTES)
                : "memory");
            asm volatile("cp.async.bulk.commit_group;" ::: "memory");
            asm volatile("cp.async.bulk.wait_group.read 0;" ::: "memory");
        }
    } else {
        // partial tail tile: scalar coalesced fallback
        const int total = npts * SH_K;
        for (int i = t; i < total; i += THREADS) {
            gbase[i] = sh[i];
        }
    }
}

extern "C" void kernel_launch(void* const* d_in, const int* in_sizes, int n_in,
                              void* d_out, int out_size) {
    const float* coords = (const float*)d_in[0];
    float* out = (float*)d_out;
    const int n = in_sizes[0] / 3;

    cudaFuncSetAttribute(sph_harm_kernel,
                         cudaFuncAttributeMaxDynamicSharedMemorySize, SMEM_BYTES);
    cudaFuncSetAttribute(sph_harm_kernel,
                         cudaFuncAttributePreferredSharedMemoryCarveout, 100);

    const int blocks = (n + TILE - 1) / TILE;
    sph_harm_kernel<<<blocks, THREADS, SMEM_BYTES>>>(coords, out, n);
}

// round 9
// speedup vs baseline: 1.0486x; 1.0486x over previous
#include <cuda_runtime.h>
#include <cuda_bf16.h>
#include <cstdint>

// Real spherical harmonics up to L=20 -> 441 cols/point, N=500k, fp32 out.
// 882 MB of output => HBM-write-bound (~110us floor at 8 TB/s spec;
// measured practical write ceiling ~6.6-7.0 TB/s on this part).
//
// Round-9 = round-6 (best: 126.5us) + L2::cache_hint evict_first on the
// bulk store: output is write-once/never-read; evict-first lets L2 drain
// dirty lines to DRAM eagerly instead of holding them at normal priority.
// Everything else identical to the proven r6 structure:
//  - TILE=32 points/CTA, 128 threads: 4 threads/point split by m mod 4.
//  - Non-persistent grid (15625 CTAs, retirement-staggered store phases).
//  - All recurrence coefficients + norms are compile-time immediates (no LDC).
//  - Scatter STS (stride 441 words, odd => bank-conflict-free).
//  - smem 56448 B -> 4 CTAs/SM; one bulk TMA store per tile;
//    wait_group.read 0 (smem-read completion only) before CTA exit.

#define SH_L 20
#define SH_K 441
#define TILE 32
#define THREADS 128
#define SMEM_BYTES (TILE * SH_K * 4)   // 56448

// ---------- compile-time math ----------
__host__ __device__ constexpr double kPI_c() { return 3.141592653589793238462643383279502884; }

__host__ __device__ constexpr double csqrt(double x) {
    double g = (x > 1.0) ? x : 1.0;
    for (int i = 0; i < 200; ++i) g = 0.5 * (g + x / g);
    return g;
}

__host__ __device__ constexpr double inv_ratio(int l, int m) {
    double p = 1.0;
    for (int k = l - m + 1; k <= l + m; ++k) p *= (double)k;
    return p;
}

template <int L_, int M>
__host__ __device__ constexpr float nf_val() {
    double norm = csqrt((2.0 * L_ + 1.0) / (4.0 * kPI_c()) / inv_ratio(L_, M));
    return (float)(M > 0 ? norm * csqrt(2.0) : norm);
}

// ---------- store helpers ----------
template <int M, int L_>
__device__ __forceinline__ void storepair(float* __restrict__ row, float b,
                                          float cm, float sm) {
    if constexpr (M == 0) {
        row[L_ * (L_ + 1)] = b;
    } else {
        row[L_ * (L_ + 1) + M] = b * cm;
        row[L_ * (L_ + 1) - M] = b * sm;
    }
}

// ---------- l recursion for fixed m ----------
template <int M, int L_>
__device__ __forceinline__ void lstep(float* __restrict__ row, float ct,
                                      float cm, float sm, float p1, float p2) {
    constexpr float A = (float)((double)(2 * L_ - 1) / (double)(L_ - M));
    constexpr float B = (float)(-(double)(L_ + M - 1) / (double)(L_ - M));
    const float pv = fmaf(A * ct, p1, B * p2);
    constexpr float NF = nf_val<L_, M>();
    storepair<M, L_>(row, NF * pv, cm, sm);
    if constexpr (L_ < SH_L) lstep<M, L_ + 1>(row, ct, cm, sm, pv, p1);
}

// ---------- m chain: one residue class mod 4 ----------
template <int M>
__device__ __forceinline__ void mchain(float* __restrict__ row, float ct,
                                       float st4, float c4, float s4,
                                       float pmm, float cm, float sm) {
    constexpr float NF0 = nf_val<M, M>();
    storepair<M, M>(row, NF0 * pmm, cm, sm);
    if constexpr (M < SH_L) {
        constexpr float C1 = (float)(2 * M + 1);
        const float p1 = (C1 * ct) * pmm;
        constexpr float NF1 = nf_val<M + 1, M>();
        storepair<M, M + 1>(row, NF1 * p1, cm, sm);
        if constexpr (M + 2 <= SH_L) lstep<M, M + 2>(row, ct, cm, sm, p1, pmm);
    }
    if constexpr (M + 4 <= SH_L) {
        constexpr float F = (float)((double)(2 * M + 1) * (2 * M + 3) *
                                    (2 * M + 5) * (2 * M + 7));
        const float pmm2 = (pmm * F) * st4;
        const float cn = fmaf(cm, c4, -(sm * s4));
        const float sn = fmaf(sm, c4, cm * s4);
        mchain<M + 4>(row, ct, st4, c4, s4, pmm2, cn, sn);
    }
}

__device__ __forceinline__ uint32_t smem_u32(const void* p) {
    uint32_t a;
    asm("{ .reg .u64 t; cvta.to.shared.u64 t, %1; cvt.u32.u64 %0, t; }"
        : "=r"(a) : "l"(p));
    return a;
}

// ---------- kernel ----------
__global__ void __launch_bounds__(THREADS, 4)
sph_harm_kernel(const float* __restrict__ coords, float* __restrict__ out, int n)
{
    extern __shared__ float sh[];           // TILE * SH_K floats
    const int base = blockIdx.x * TILE;
    const int t = threadIdx.x;
    const int lane = t & 31;                // point within tile
    const int w = t >> 5;                   // m residue (0..3)
    const int p = base + lane;

    if (p < n) {
        const float x = coords[3 * p + 0];
        const float y = coords[3 * p + 1];
        const float z = coords[3 * p + 2];

        const float r = sqrtf(x * x + y * y + z * z);
        float ct = z / r;
        ct = fminf(1.0f, fmaxf(-1.0f, ct));
        const float st = sqrtf(fmaxf(1.0f - ct * ct, 0.0f));
        const float st2 = st * st;
        const float st4 = st2 * st2;

        const float rho2 = x * x + y * y;
        float c1, s1;
        if (rho2 > 0.0f) {
            const float ir = rsqrtf(rho2);
            c1 = x * ir;
            s1 = y * ir;
        } else {
            c1 = 1.0f;
            s1 = 0.0f;
        }
        const float c2 = fmaf(c1, c1, -(s1 * s1));
        const float s2 = 2.0f * c1 * s1;
        const float c3 = fmaf(c2, c1, -(s2 * s1));
        const float s3 = fmaf(s2, c1, c2 * s1);
        const float c4 = fmaf(c2, c2, -(s2 * s2));
        const float s4 = 2.0f * c2 * s2;

        float* row = sh + lane * SH_K;

        if (w == 0) {
            mchain<0>(row, ct, st4, c4, s4, 1.0f, 1.0f, 0.0f);
        } else if (w == 1) {
            mchain<1>(row, ct, st4, c4, s4, -st, c1, s1);
        } else if (w == 2) {
            const float pmm = (3.0f * st) * st;                 // P_2^2
            mchain<2>(row, ct, st4, c4, s4, pmm, c2, s2);
        } else {
            const float pmm = ((-15.0f * st) * st) * st;        // P_3^3
            mchain<3>(row, ct, st4, c4, s4, pmm, c3, s3);
        }
    }

    // make STS visible to the async proxy, then sync the tile
    asm volatile("fence.proxy.async.shared::cta;" ::: "memory");
    __syncthreads();

    const int npts = min(TILE, n - base);
    if (npts <= 0) return;
    float* gbase = out + (size_t)base * SH_K;

    if (npts == TILE) {
        // full tile: single bulk TMA store (56448 B, 128B-aligned at GMEM),
        // evict-first L2 policy (write-once data, drain eagerly to DRAM).
        if (t == 0) {
            const uint32_t saddr = smem_u32(sh);
            uint64_t pol;
            asm volatile("createpolicy.fractional.L2::evict_first.b64 %0, 1.0;"
                         : "=l"(pol));
            asm volatile(
                "cp.async.bulk.global.shared::cta.bulk_group.L2::cache_hint "
                "[%0], [%1], %2, %3;"
                :: "l"(gbase), "r"(saddr), "r"((uint32_t)SMEM_BYTES), "l"(pol)
                : "memory");
            asm volatile("cp.async.bulk.commit_group;" ::: "memory");
            asm volatile("cp.async.bulk.wait_group.read 0;" ::: "memory");
        }
    } else {
        // partial tail tile: scalar coalesced fallback
        const int total = npts * SH_K;
        for (int i = t; i < total; i += THREADS) {
            gbase[i] = sh[i];
        }
    }
}

extern "C" void kernel_launch(void* const* d_in, const int* in_sizes, int n_in,
                              void* d_out, int out_size) {
    const float* coords = (const float*)d_in[0];
    float* out = (float*)d_out;
    const int n = in_sizes[0] / 3;

    cudaFuncSetAttribute(sph_harm_kernel,
                         cudaFuncAttributeMaxDynamicSharedMemorySize, SMEM_BYTES);
    cudaFuncSetAttribute(sph_harm_kernel,
                         cudaFuncAttributePreferredSharedMemoryCarveout, 100);

    const int blocks = (n + TILE - 1) / TILE;
    sph_harm_kernel<<<blocks, THREADS, SMEM_BYTES>>>(coords, out, n);
}

// round 11
// speedup vs baseline: 1.0511x; 1.0024x over previous
#include <cuda_runtime.h>
#include <cuda_bf16.h>
#include <cstdint>

// Real spherical harmonics up to L=20 -> 441 cols/point, N=500k, fp32 out.
// 882 MB of output => HBM-write-bound.
//
// Round-11 = round-9 (best: 121.2us, evict_first hint) with the tile store
// split into TWO 28224 B bulk-TMA commands issued by two threads (t=0,t=32),
// each with its own bulk_group commit + read-wait: gives the SM's TMA engine
// request-level parallelism and interleaves the two halves' smem read-out.
// (no_allocate primary is not encodable in createpolicy.fractional -> stick
// with the proven evict_first.)
// Everything else identical to r9:
//  - TILE=32 points/CTA, 128 threads: 4 threads/point split by m mod 4.
//  - Non-persistent grid (15625 CTAs, retirement-staggered store phases).
//  - All recurrence coefficients + norms are compile-time immediates (no LDC).
//  - Scatter STS (stride 441 words, odd => bank-conflict-free).
//  - smem 56448 B -> 4 CTAs/SM; wait_group.read 0 before CTA exit.

#define SH_L 20
#define SH_K 441
#define TILE 32
#define THREADS 128
#define SMEM_BYTES (TILE * SH_K * 4)   // 56448
#define HALF_BYTES (SMEM_BYTES / 2)    // 28224

// ---------- compile-time math ----------
__host__ __device__ constexpr double kPI_c() { return 3.141592653589793238462643383279502884; }

__host__ __device__ constexpr double csqrt(double x) {
    double g = (x > 1.0) ? x : 1.0;
    for (int i = 0; i < 200; ++i) g = 0.5 * (g + x / g);
    return g;
}

__host__ __device__ constexpr double inv_ratio(int l, int m) {
    double p = 1.0;
    for (int k = l - m + 1; k <= l + m; ++k) p *= (double)k;
    return p;
}

template <int L_, int M>
__host__ __device__ constexpr float nf_val() {
    double norm = csqrt((2.0 * L_ + 1.0) / (4.0 * kPI_c()) / inv_ratio(L_, M));
    return (float)(M > 0 ? norm * csqrt(2.0) : norm);
}

// ---------- store helpers ----------
template <int M, int L_>
__device__ __forceinline__ void storepair(float* __restrict__ row, float b,
                                          float cm, float sm) {
    if constexpr (M == 0) {
        row[L_ * (L_ + 1)] = b;
    } else {
        row[L_ * (L_ + 1) + M] = b * cm;
        row[L_ * (L_ + 1) - M] = b * sm;
    }
}

// ---------- l recursion for fixed m ----------
template <int M, int L_>
__device__ __forceinline__ void lstep(float* __restrict__ row, float ct,
                                      float cm, float sm, float p1, float p2) {
    constexpr float A = (float)((double)(2 * L_ - 1) / (double)(L_ - M));
    constexpr float B = (float)(-(double)(L_ + M - 1) / (double)(L_ - M));
    const float pv = fmaf(A * ct, p1, B * p2);
    constexpr float NF = nf_val<L_, M>();
    storepair<M, L_>(row, NF * pv, cm, sm);
    if constexpr (L_ < SH_L) lstep<M, L_ + 1>(row, ct, cm, sm, pv, p1);
}

// ---------- m chain: one residue class mod 4 ----------
template <int M>
__device__ __forceinline__ void mchain(float* __restrict__ row, float ct,
                                       float st4, float c4, float s4,
                                       float pmm, float cm, float sm) {
    constexpr float NF0 = nf_val<M, M>();
    storepair<M, M>(row, NF0 * pmm, cm, sm);
    if constexpr (M < SH_L) {
        constexpr float C1 = (float)(2 * M + 1);
        const float p1 = (C1 * ct) * pmm;
        constexpr float NF1 = nf_val<M + 1, M>();
        storepair<M, M + 1>(row, NF1 * p1, cm, sm);
        if constexpr (M + 2 <= SH_L) lstep<M, M + 2>(row, ct, cm, sm, p1, pmm);
    }
    if constexpr (M + 4 <= SH_L) {
        constexpr float F = (float)((double)(2 * M + 1) * (2 * M + 3) *
                                    (2 * M + 5) * (2 * M + 7));
        const float pmm2 = (pmm * F) * st4;
        const float cn = fmaf(cm, c4, -(sm * s4));
        const float sn = fmaf(sm, c4, cm * s4);
        mchain<M + 4>(row, ct, st4, c4, s4, pmm2, cn, sn);
    }
}

__device__ __forceinline__ uint32_t smem_u32(const void* p) {
    uint32_t a;
    asm("{ .reg .u64 t; cvta.to.shared.u64 t, %1; cvt.u32.u64 %0, t; }"
        : "=r"(a) : "l"(p));
    return a;
}

// ---------- kernel ----------
__global__ void __launch_bounds__(THREADS, 4)
sph_harm_kernel(const float* __restrict__ coords, float* __restrict__ out, int n)
{
    extern __shared__ float sh[];           // TILE * SH_K floats
    const int base = blockIdx.x * TILE;
    const int t = threadIdx.x;
    const int lane = t & 31;                // point within tile
    const int w = t >> 5;                   // m residue (0..3)
    const int p = base + lane;

    if (p < n) {
        const float x = coords[3 * p + 0];
        const float y = coords[3 * p + 1];
        const float z = coords[3 * p + 2];

        const float r = sqrtf(x * x + y * y + z * z);
        float ct = z / r;
        ct = fminf(1.0f, fmaxf(-1.0f, ct));
        const float st = sqrtf(fmaxf(1.0f - ct * ct, 0.0f));
        const float st2 = st * st;
        const float st4 = st2 * st2;

        const float rho2 = x * x + y * y;
        float c1, s1;
        if (rho2 > 0.0f) {
            const float ir = rsqrtf(rho2);
            c1 = x * ir;
            s1 = y * ir;
        } else {
            c1 = 1.0f;
            s1 = 0.0f;
        }
        const float c2 = fmaf(c1, c1, -(s1 * s1));
        const float s2 = 2.0f * c1 * s1;
        const float c3 = fmaf(c2, c1, -(s2 * s1));
        const float s3 = fmaf(s2, c1, c2 * s1);
        const float c4 = fmaf(c2, c2, -(s2 * s2));
        const float s4 = 2.0f * c2 * s2;

        float* row = sh + lane * SH_K;

        if (w == 0) {
            mchain<0>(row, ct, st4, c4, s4, 1.0f, 1.0f, 0.0f);
        } else if (w == 1) {
            mchain<1>(row, ct, st4, c4, s4, -st, c1, s1);
        } else if (w == 2) {
            const float pmm = (3.0f * st) * st;                 // P_2^2
            mchain<2>(row, ct, st4, c4, s4, pmm, c2, s2);
        } else {
            const float pmm = ((-15.0f * st) * st) * st;        // P_3^3
            mchain<3>(row, ct, st4, c4, s4, pmm, c3, s3);
        }
    }

    // make STS visible to the async proxy, then sync the tile
    asm volatile("fence.proxy.async.shared::cta;" ::: "memory");
    __syncthreads();

    const int npts = min(TILE, n - base);
    if (npts <= 0) return;
    float* gbase = out + (size_t)base * SH_K;

    if (npts == TILE) {
        // full tile: TWO 28224 B bulk TMA stores (evict_first L2 policy),
        // issued by t=0 and t=32; each thread commits + read-waits its own
        // bulk group -> TMA engine gets two independent commands.
        if ((t & 31) == 0 && t < 64) {
            const int half = t >> 5;        // 0 or 1
            const uint32_t saddr = smem_u32(sh) + half * HALF_BYTES;
            float* gdst = gbase + half * (HALF_BYTES / 4);
            uint64_t pol;
            asm volatile("createpolicy.fractional.L2::evict_first.b64 %0, 1.0;"
                         : "=l"(pol));
            asm volatile(
                "cp.async.bulk.global.shared::cta.bulk_group.L2::cache_hint "
                "[%0], [%1], %2, %3;"
                :: "l"(gdst), "r"(saddr), "r"((uint32_t)HALF_BYTES), "l"(pol)
                : "memory");
            asm volatile("cp.async.bulk.commit_group;" ::: "memory");
            asm volatile("cp.async.bulk.wait_group.read 0;" ::: "memory");
        }
    } else {
        // partial tail tile: scalar coalesced fallback
        const int total = npts * SH_K;
        for (int i = t; i < total; i += THREADS) {
            gbase[i] = sh[i];
        }
    }
}

extern "C" void kernel_launch(void* const* d_in, const int* in_sizes, int n_in,
                              void* d_out, int out_size) {
    const float* coords = (const float*)d_in[0];
    float* out = (float*)d_out;
    const int n = in_sizes[0] / 3;

    cudaFuncSetAttribute(sph_harm_kernel,
                         cudaFuncAttributeMaxDynamicSharedMemorySize, SMEM_BYTES);
    cudaFuncSetAttribute(sph_harm_kernel,
                         cudaFuncAttributePreferredSharedMemoryCarveout, 100);

    const int blocks = (n + TILE - 1) / TILE;
    sph_harm_kernel<<<blocks, THREADS, SMEM_BYTES>>>(coords, out, n);
}